// round 16
// baseline (speedup 1.0000x reference)
#include <cuda_runtime.h>
#include <cuda_bf16.h>
#include <math.h>

#define NN 50000
#define EE 800000
#define FF 500
#define SW 576        // hop-2 state per node: 512 (M1) + 64 (Kf1)
#define SW4 144       // state width in float4 (fp32) / uint2 (bf16)
#define CSTV 1e-5f
#define PROBE_N 12500 // NN/4 — diagnostic replica of spmm2 mainloop

// ---------------- static device scratch (no runtime allocation) ----------------
__device__ __align__(16) float g_x[(size_t)NN * 64];
__device__ __align__(16) float g_Q[(size_t)NN * 64];
__device__ __align__(16) float g_kv[(size_t)NN * 96];          // [0..63]=Kf0, [64..95]=V0 (fp32)
__device__ __align__(16) __nv_bfloat16 g_sb[(size_t)NN * SW];  // [M1 | Kf1] in bf16
__device__ __align__(16) float g_hidden[(size_t)NN * 32];
__device__ int   g_deg[NN];
__device__ float g_dinv[NN];
__device__ int   g_off[NN + 1];
__device__ int   g_cnt[NN];
__device__ __align__(16) uint2 g_epk[EE];   // per edge: (src, __float_as_uint(scale))
__device__ float g_tele[SW];     // teleport sums: 512 of M0, 64 of Kf0
__device__ int   g_is64;         // edge_index dtype flag (1 = int64, 0 = int32)

// ---------------- dtype detection (warp-parallel) ----------------
__global__ void k_detect(const void* __restrict__ ei) {
    const long long* p = (const long long*)ei;
    int t = threadIdx.x;
    int bad = 0;
    for (int i = t; i < 1024; i += 32) {
        long long v = p[i];
        if (v < 0 || v >= NN) bad = 1;
    }
    unsigned m = __ballot_sync(0xFFFFFFFFu, bad);
    if (t == 0) g_is64 = (m == 0) ? 1 : 0;
}

__device__ __forceinline__ int edge_at(const void* __restrict__ ei, int half, int e, int is64) {
    if (is64) return (int)((const long long*)ei)[(size_t)half * EE + e];
    return ((const int*)ei)[(size_t)half * EE + e];
}

// ---------------- zero counters ----------------
__global__ void k_zero() {
    int i = blockIdx.x * blockDim.x + threadIdx.x;
    if (i < NN) { g_deg[i] = 0; g_cnt[i] = 0; }
    if (i < SW) g_tele[i] = 0.f;
}

// ---------------- in-degree over col ----------------
__global__ void k_deg(const void* __restrict__ ei) {
    int e = blockIdx.x * blockDim.x + threadIdx.x;
    int is64 = g_is64;
    if (e < EE) atomicAdd(&g_deg[edge_at(ei, 1, e, is64)], 1);
}

// ---------------- deg^-1 ----------------
__global__ void k_dinv() {
    int i = blockIdx.x * blockDim.x + threadIdx.x;
    if (i < NN) {
        int d = g_deg[i];
        g_dinv[i] = d > 0 ? 1.f / (float)d : 0.f;
    }
}

// ---------------- exclusive scan of deg -> CSR offsets (single block) ----------------
__global__ void k_scan() {
    __shared__ int s[1024];
    int tid = threadIdx.x;
    const int CH = (NN + 1023) / 1024;
    int st = tid * CH;
    int en = st + CH; if (en > NN) en = NN;
    int sum = 0;
    for (int i = st; i < en; i++) sum += g_deg[i];
    s[tid] = sum;
    __syncthreads();
    for (int d = 1; d < 1024; d <<= 1) {
        int v = 0;
        if (tid >= d) v = s[tid - d];
        __syncthreads();
        if (tid >= d) s[tid] += v;
        __syncthreads();
    }
    int run = (tid > 0) ? s[tid - 1] : 0;
    for (int i = st; i < en; i++) { g_off[i] = run; run += g_deg[i]; }
    if (tid == 1023) g_off[NN] = s[1023];
}

// ---------------- fill CSR (grouped by destination) + packed per-edge meta ----------------
__global__ void k_fill(const void* __restrict__ ei) {
    int e = blockIdx.x * blockDim.x + threadIdx.x;
    int is64 = g_is64;
    if (e < EE) {
        int c = edge_at(ei, 1, e, is64);
        int r = edge_at(ei, 0, e, is64);
        int pos = g_off[c] + atomicAdd(&g_cnt[c], 1);
        g_epk[pos] = make_uint2((unsigned)r, __float_as_uint(g_dinv[r]));  // norm = deg_inv[row[e]]
    }
}

__device__ __forceinline__ float2 bf2f(unsigned u) {
    return __bfloat1622float2(*reinterpret_cast<__nv_bfloat162*>(&u));
}

// ---------------- DIAGNOSTIC PROBE: spmm2 mainloop replica (slot 4 -> ncu) ----------------
// Self-sufficient: synthetic uniform-random source rows (address mix depends on g_epk
// values only additively — zeros on call 1), same dependent LDG chain, same gather
// shape and FMA/convert mix as k_spmm2's mainloop. Writes to g_x (overwritten by
// k_gemm1 at slot 5), so the final output is unaffected.
__global__ void __launch_bounds__(160) k_probe() {
    int n = blockIdx.x;
    int t = threadIdx.x;
    float4 acc = make_float4(0.f, 0.f, 0.f, 0.f);
    if (t < SW4) {
        unsigned base = (unsigned)n * 2654435761u;
        #pragma unroll 1
        for (int e = 0; e < 16; e += 2) {
            uint2 m0 = __ldg(&g_epk[(n * 16 + e) % EE]);       // broadcast meta load (dep chain)
            uint2 m1 = __ldg(&g_epk[(n * 16 + e + 1) % EE]);
            unsigned s0i = (m0.x + base + (unsigned)e * 40503u) % NN;
            unsigned s1i = (m1.x + base + (unsigned)(e + 1) * 40503u) % NN;
            float c0 = __uint_as_float(m0.y) + 0.5f;
            float c1 = __uint_as_float(m1.y) + 0.25f;
            uint2 u0 = __ldg((const uint2*)(g_sb + (size_t)s0i * SW) + t);
            uint2 u1 = __ldg((const uint2*)(g_sb + (size_t)s1i * SW) + t);
            float2 a0 = bf2f(u0.x), b0 = bf2f(u0.y);
            float2 a1 = bf2f(u1.x), b1 = bf2f(u1.y);
            acc.x = fmaf(c0, a0.x, fmaf(c1, a1.x, acc.x));
            acc.y = fmaf(c0, a0.y, fmaf(c1, a1.y, acc.y));
            acc.z = fmaf(c0, b0.x, fmaf(c1, b1.x, acc.z));
            acc.w = fmaf(c0, b0.y, fmaf(c1, b1.y, acc.w));
        }
        float s = acc.x + acc.y + acc.z + acc.w;
        #pragma unroll
        for (int off = 16; off >= 1; off >>= 1)
            s += __shfl_xor_sync(0xFFFFFFFFu, s, off);
        if ((t & 31) == 0)
            g_x[(size_t)n * 5 + (t >> 5)] = s;    // kept live; g_gemm1 overwrites g_x fully
    }
}

// ---------------- x = relu(node_feat @ Wi + bi)   [N,500]x[500,64] ----------------
__global__ void __launch_bounds__(256) k_gemm1(const float* __restrict__ A,
                                               const float* __restrict__ Wi,
                                               const float* __restrict__ bi) {
    __shared__ float As[64][33];
    __shared__ __align__(16) float Bs[32 * 64];
    int tid = threadIdx.x;
    int row0 = blockIdx.x * 64;
    int tc = tid & 15;
    int tr = tid >> 4;
    float acc[4][4];
    #pragma unroll
    for (int i = 0; i < 4; i++)
        #pragma unroll
        for (int j = 0; j < 4; j++) acc[i][j] = 0.f;

    for (int k0 = 0; k0 < FF; k0 += 32) {
        #pragma unroll
        for (int it = 0; it < 8; it++) {
            int idx = tid + it * 256;
            int r = idx >> 5, kk = idx & 31;
            int gr = row0 + r, gk = k0 + kk;
            As[r][kk] = (gr < NN && gk < FF) ? A[(size_t)gr * FF + gk] : 0.f;
        }
        #pragma unroll
        for (int it = 0; it < 8; it++) {
            int idx = tid + it * 256;
            int kk = idx >> 6, c = idx & 63;
            int gk = k0 + kk;
            Bs[idx] = (gk < FF) ? Wi[gk * 64 + c] : 0.f;
        }
        __syncthreads();
        #pragma unroll
        for (int kk = 0; kk < 32; kk++) {
            float a[4];
            #pragma unroll
            for (int i = 0; i < 4; i++) a[i] = As[tr * 4 + i][kk];
            float4 bv = *(const float4*)&Bs[kk * 64 + tc * 4];
            float b[4] = {bv.x, bv.y, bv.z, bv.w};
            #pragma unroll
            for (int i = 0; i < 4; i++)
                #pragma unroll
                for (int j = 0; j < 4; j++)
                    acc[i][j] = fmaf(a[i], b[j], acc[i][j]);
        }
        __syncthreads();
    }
    #pragma unroll
    for (int i = 0; i < 4; i++) {
        int r = row0 + tr * 4 + i;
        if (r < NN) {
            #pragma unroll
            for (int j = 0; j < 4; j++) {
                int c = tc * 4 + j;
                float v = acc[i][j] + bi[c];
                g_x[(size_t)r * 64 + c] = v > 0.f ? v : 0.f;
            }
        }
    }
}

// ---------------- fused QKV projections  [N,64]x[64,160] ----------------
// cols 0..63 -> Q (1+elu), 64..127 -> Kf0 (1+elu, kv[0..63]), 128..159 -> V0 (kv[64..95])
__global__ void __launch_bounds__(256) k_gemm2(const float* __restrict__ Wq, const float* __restrict__ bq,
                                               const float* __restrict__ Wk, const float* __restrict__ bk,
                                               const float* __restrict__ Wv, const float* __restrict__ bv) {
    __shared__ float Xs[64][33];
    __shared__ float Ws[32][160];
    int tid = threadIdx.x;
    int row0 = blockIdx.x * 64;
    int tc = tid & 15;
    int tr = tid >> 4;
    float acc[4][10];
    #pragma unroll
    for (int i = 0; i < 4; i++)
        #pragma unroll
        for (int j = 0; j < 10; j++) acc[i][j] = 0.f;

    for (int kt = 0; kt < 2; kt++) {
        #pragma unroll
        for (int it = 0; it < 8; it++) {
            int idx = tid + it * 256;
            int r = idx >> 5, kk = idx & 31;
            int gr = row0 + r;
            Xs[r][kk] = (gr < NN) ? g_x[(size_t)gr * 64 + kt * 32 + kk] : 0.f;
        }
        #pragma unroll
        for (int it = 0; it < 20; it++) {
            int idx = tid + it * 256;
            int kk = idx / 160, c = idx % 160;
            int gk = kt * 32 + kk;
            float w;
            if (c < 64)       w = Wq[gk * 64 + c];
            else if (c < 128) w = Wk[gk * 64 + (c - 64)];
            else              w = Wv[gk * 32 + (c - 128)];
            Ws[kk][c] = w;
        }
        __syncthreads();
        #pragma unroll
        for (int kk = 0; kk < 32; kk++) {
            float a[4];
            #pragma unroll
            for (int i = 0; i < 4; i++) a[i] = Xs[tr * 4 + i][kk];
            float b[10];
            #pragma unroll
            for (int j = 0; j < 10; j++) b[j] = Ws[kk][tc * 10 + j];
            #pragma unroll
            for (int i = 0; i < 4; i++)
                #pragma unroll
                for (int j = 0; j < 10; j++)
                    acc[i][j] = fmaf(a[i], b[j], acc[i][j]);
        }
        __syncthreads();
    }

    #pragma unroll
    for (int i = 0; i < 4; i++) {
        int r = row0 + tr * 4 + i;
        if (r >= NN) continue;
        #pragma unroll
        for (int j = 0; j < 10; j++) {
            int c = tc * 10 + j;
            float v = acc[i][j];
            if (c < 64) {
                v += bq[c];
                v = v > 0.f ? 1.f + v : expf(v);   // 1 + elu
                g_Q[(size_t)r * 64 + c] = v;
            } else if (c < 128) {
                int cc = c - 64;
                v += bk[cc];
                v = v > 0.f ? 1.f + v : expf(v);
                g_kv[(size_t)r * 96 + cc] = v;
            } else {
                int cc = c - 128;
                v += bv[cc];
                g_kv[(size_t)r * 96 + 64 + cc] = v;
            }
        }
    }
}

// ---------------- teleport sums over M0 = Kf0 (x) V0 and Kf0 ----------------
__global__ void __launch_bounds__(576) k_tele() {
    __shared__ float skv[96];
    int t = threadIdx.x;
    int n0 = blockIdx.x * 32;
    float tele = 0.f;
    for (int nn = 0; nn < 32; nn++) {
        int n = n0 + nn;
        if (n >= NN) break;
        __syncthreads();
        if (t < 96) skv[t] = g_kv[(size_t)n * 96 + t];
        __syncthreads();
        if (t < 512) tele += skv[t >> 3] * skv[64 + (((t >> 7) << 3) | (t & 7))];
        else         tele += skv[t - 512];
    }
    atomicAdd(&g_tele[t], tele);
}

// ---------------- hop 1: rank-1 on-the-fly gather (fp32 kv, packed edge meta) ----------------
// 160 threads, one block per destination. Thread t<144 owns state float4 t of [M1|Kf1].
__global__ void __launch_bounds__(160) k_spmm1(const float* __restrict__ hopwise,
                                               const float* __restrict__ headwise) {
    __shared__ float sQ[64];
    __shared__ float sHh[32];
    __shared__ float sCc[4];
    __shared__ float sG[4];
    int n = blockIdx.x;
    int t = threadIdx.x;

    if (t < 4) {   // gamma0[h] = hopwise[1] * softmax_h(headwise[:,0])[h]
        float w0 = headwise[0], w1 = headwise[2], w2 = headwise[4], w3 = headwise[6];
        float mx = fmaxf(fmaxf(w0, w1), fmaxf(w2, w3));
        float e0 = expf(w0 - mx), e1 = expf(w1 - mx), e2 = expf(w2 - mx), e3 = expf(w3 - mx);
        float inv = 1.f / (e0 + e1 + e2 + e3);
        float me = (t == 0) ? e0 : (t == 1) ? e1 : (t == 2) ? e2 : e3;
        sG[t] = hopwise[1] * me * inv;
    }
    if (t >= 32 && t < 96) sQ[t - 32] = g_Q[(size_t)n * 64 + (t - 32)];

    int beg = g_off[n], end = g_off[n + 1];
    float4 acc = make_float4(0.f, 0.f, 0.f, 0.f);

    if (t < 128) {
        int kidx  = t >> 1;                         // Kf0 scalar index h*16+i
        int v4idx = 16 + ((t >> 5) << 1) + (t & 1); // V0 float4 index within 24-float4 row
        int e = beg;
        for (; e + 1 < end; e += 2) {
            uint2 m0 = __ldg(&g_epk[e]);
            uint2 m1 = __ldg(&g_epk[e + 1]);
            int   s0i = (int)m0.x;
            int   s1i = (int)m1.x;
            float c0  = __uint_as_float(m0.y);
            float c1  = __uint_as_float(m1.y);
            const float4* r0 = (const float4*)(g_kv + (size_t)s0i * 96);
            const float4* r1 = (const float4*)(g_kv + (size_t)s1i * 96);
            float k0 = __ldg((const float*)r0 + kidx);
            float k1 = __ldg((const float*)r1 + kidx);
            float4 v0 = __ldg(r0 + v4idx);
            float4 v1 = __ldg(r1 + v4idx);
            float sk0 = c0 * k0, sk1 = c1 * k1;
            acc.x = fmaf(sk0, v0.x, fmaf(sk1, v1.x, acc.x));
            acc.y = fmaf(sk0, v0.y, fmaf(sk1, v1.y, acc.y));
            acc.z = fmaf(sk0, v0.z, fmaf(sk1, v1.z, acc.z));
            acc.w = fmaf(sk0, v0.w, fmaf(sk1, v1.w, acc.w));
        }
        if (e < end) {
            uint2 m = __ldg(&g_epk[e]);
            int   si = (int)m.x;
            float c  = __uint_as_float(m.y);
            const float4* r = (const float4*)(g_kv + (size_t)si * 96);
            float sk = c * __ldg((const float*)r + kidx);
            float4 v = __ldg(r + v4idx);
            acc.x = fmaf(sk, v.x, acc.x);
            acc.y = fmaf(sk, v.y, acc.y);
            acc.z = fmaf(sk, v.z, acc.z);
            acc.w = fmaf(sk, v.w, acc.w);
        }
    } else if (t < 144) {
        int k4 = t - 128;                           // Kf0 float4 index
        int e = beg;
        for (; e + 1 < end; e += 2) {
            uint2 m0 = __ldg(&g_epk[e]);
            uint2 m1 = __ldg(&g_epk[e + 1]);
            int   s0i = (int)m0.x;
            int   s1i = (int)m1.x;
            float c0  = __uint_as_float(m0.y);
            float c1  = __uint_as_float(m1.y);
            float4 v0 = __ldg((const float4*)(g_kv + (size_t)s0i * 96) + k4);
            float4 v1 = __ldg((const float4*)(g_kv + (size_t)s1i * 96) + k4);
            acc.x = fmaf(c0, v0.x, fmaf(c1, v1.x, acc.x));
            acc.y = fmaf(c0, v0.y, fmaf(c1, v1.y, acc.y));
            acc.z = fmaf(c0, v0.z, fmaf(c1, v1.z, acc.z));
            acc.w = fmaf(c0, v0.w, fmaf(c1, v1.w, acc.w));
        }
        if (e < end) {
            uint2 m = __ldg(&g_epk[e]);
            int   si = (int)m.x;
            float c  = __uint_as_float(m.y);
            float4 v = __ldg((const float4*)(g_kv + (size_t)si * 96) + k4);
            acc.x = fmaf(c, v.x, acc.x);
            acc.y = fmaf(c, v.y, acc.y);
            acc.z = fmaf(c, v.z, acc.z);
            acc.w = fmaf(c, v.w, acc.w);
        }
    }

    // publish [M1|Kf1] state for hop 2 in bf16 (one 8B store per thread)
    if (t < SW4) {
        __nv_bfloat162 p0 = __floats2bfloat162_rn(acc.x, acc.y);
        __nv_bfloat162 p1 = __floats2bfloat162_rn(acc.z, acc.w);
        uint2 u;
        u.x = *reinterpret_cast<unsigned*>(&p0);
        u.y = *reinterpret_cast<unsigned*>(&p1);
        ((uint2*)(g_sb + (size_t)n * SW))[t] = u;
    }
    __syncthreads();

    // contraction (fp32 accumulators)
    if (t < 128) {
        int h = t >> 5;
        int kidx = t >> 1;
        int j0 = (t & 1) * 4;
        float q = sQ[kidx];
        float r0 = q * acc.x, r1 = q * acc.y, r2 = q * acc.z, r3 = q * acc.w;
        #pragma unroll
        for (int off = 2; off <= 16; off <<= 1) {
            r0 += __shfl_xor_sync(0xFFFFFFFFu, r0, off);
            r1 += __shfl_xor_sync(0xFFFFFFFFu, r1, off);
            r2 += __shfl_xor_sync(0xFFFFFFFFu, r2, off);
            r3 += __shfl_xor_sync(0xFFFFFFFFu, r3, off);
        }
        int lane = t & 31;
        if (lane < 2) {
            sHh[h * 8 + j0 + 0] = r0;
            sHh[h * 8 + j0 + 1] = r1;
            sHh[h * 8 + j0 + 2] = r2;
            sHh[h * 8 + j0 + 3] = r3;
        }
    } else if (t < 144) {
        int f = (t - 128) * 4;
        float c = sQ[f] * acc.x + sQ[f + 1] * acc.y + sQ[f + 2] * acc.z + sQ[f + 3] * acc.w;
        #pragma unroll
        for (int off = 1; off <= 2; off <<= 1)
            c += __shfl_xor_sync(0x0000FFFFu, c, off);
        int lane = t & 31;
        if ((lane & 3) == 0) sCc[lane >> 2] = c;
    }
    __syncthreads();

    if (t < 32) {
        int h = t >> 3;
        float v0 = g_kv[(size_t)n * 96 + 64 + t];
        g_hidden[(size_t)n * 32 + t] = hopwise[0] * v0 + sG[h] * sHh[t] / (sCc[h] + CSTV);
    }
}

// ---------------- hop 2: bf16 state gather + fused contraction (packed edge meta) ----------------
__global__ void __launch_bounds__(160) k_spmm2(const float* __restrict__ hopwise,
                                               const float* __restrict__ headwise) {
    __shared__ float sQ[64];
    __shared__ float sHh[32];
    __shared__ float sCc[4];
    __shared__ float sG[4];
    int n = blockIdx.x;
    int t = threadIdx.x;

    if (t < 4) {   // gamma1[h] = hopwise[2] * softmax_h(headwise[:,1])[h]
        float w0 = headwise[1], w1 = headwise[3], w2 = headwise[5], w3 = headwise[7];
        float mx = fmaxf(fmaxf(w0, w1), fmaxf(w2, w3));
        float e0 = expf(w0 - mx), e1 = expf(w1 - mx), e2 = expf(w2 - mx), e3 = expf(w3 - mx);
        float inv = 1.f / (e0 + e1 + e2 + e3);
        float me = (t == 0) ? e0 : (t == 1) ? e1 : (t == 2) ? e2 : e3;
        sG[t] = hopwise[2] * me * inv;
    }
    if (t >= 32 && t < 96) sQ[t - 32] = g_Q[(size_t)n * 64 + (t - 32)];

    int beg = g_off[n], end = g_off[n + 1];
    float4 acc = make_float4(0.f, 0.f, 0.f, 0.f);
    if (t < SW4) {
        int e = beg;
        for (; e + 1 < end; e += 2) {
            uint2 m0 = __ldg(&g_epk[e]);
            uint2 m1 = __ldg(&g_epk[e + 1]);
            int   s0i = (int)m0.x;
            int   s1i = (int)m1.x;
            float c0  = __uint_as_float(m0.y);
            float c1  = __uint_as_float(m1.y);
            uint2 u0 = __ldg((const uint2*)(g_sb + (size_t)s0i * SW) + t);
            uint2 u1 = __ldg((const uint2*)(g_sb + (size_t)s1i * SW) + t);
            float2 a0 = bf2f(u0.x), b0 = bf2f(u0.y);
            float2 a1 = bf2f(u1.x), b1 = bf2f(u1.y);
            acc.x = fmaf(c0, a0.x, fmaf(c1, a1.x, acc.x));
            acc.y = fmaf(c0, a0.y, fmaf(c1, a1.y, acc.y));
            acc.z = fmaf(c0, b0.x, fmaf(c1, b1.x, acc.z));
            acc.w = fmaf(c0, b0.y, fmaf(c1, b1.y, acc.w));
        }
        if (e < end) {
            uint2 m = __ldg(&g_epk[e]);
            int   si = (int)m.x;
            float c  = __uint_as_float(m.y);
            uint2 u = __ldg((const uint2*)(g_sb + (size_t)si * SW) + t);
            float2 a = bf2f(u.x), b = bf2f(u.y);
            acc.x = fmaf(c, a.x, acc.x);
            acc.y = fmaf(c, a.y, acc.y);
            acc.z = fmaf(c, b.x, acc.z);
            acc.w = fmaf(c, b.y, acc.w);
        }
    }
    __syncthreads();

    if (t < 128) {
        int h = t >> 5;
        int kidx = t >> 1;
        int j0 = (t & 1) * 4;
        float q = sQ[kidx];
        float r0 = q * acc.x, r1 = q * acc.y, r2 = q * acc.z, r3 = q * acc.w;
        #pragma unroll
        for (int off = 2; off <= 16; off <<= 1) {
            r0 += __shfl_xor_sync(0xFFFFFFFFu, r0, off);
            r1 += __shfl_xor_sync(0xFFFFFFFFu, r1, off);
            r2 += __shfl_xor_sync(0xFFFFFFFFu, r2, off);
            r3 += __shfl_xor_sync(0xFFFFFFFFu, r3, off);
        }
        int lane = t & 31;
        if (lane < 2) {
            sHh[h * 8 + j0 + 0] = r0;
            sHh[h * 8 + j0 + 1] = r1;
            sHh[h * 8 + j0 + 2] = r2;
            sHh[h * 8 + j0 + 3] = r3;
        }
    } else if (t < 144) {
        int f = (t - 128) * 4;
        float c = sQ[f] * acc.x + sQ[f + 1] * acc.y + sQ[f + 2] * acc.z + sQ[f + 3] * acc.w;
        #pragma unroll
        for (int off = 1; off <= 2; off <<= 1)
            c += __shfl_xor_sync(0x0000FFFFu, c, off);
        int lane = t & 31;
        if ((lane & 3) == 0) sCc[lane >> 2] = c;
    }
    __syncthreads();

    if (t < 32) {
        int h = t >> 3;
        g_hidden[(size_t)n * 32 + t] += sG[h] * sHh[t] / (sCc[h] + CSTV);
    }
}

// ---------------- output projection + teleport term ----------------
__global__ void __launch_bounds__(256) k_out(const float* __restrict__ Wo,
                                             const float* __restrict__ bo,
                                             const float* __restrict__ teleport,
                                             float* __restrict__ out) {
    __shared__ float sTele[SW];
    __shared__ float sWo[32 * 8];
    __shared__ float sQ[32][64];
    __shared__ float sH[32][32];
    int tid = threadIdx.x;
    int n0 = blockIdx.x * 32;

    #pragma unroll
    for (int it = 0; it < 3; it++) {
        int idx = tid + it * 256;
        if (idx < SW) sTele[idx] = g_tele[idx] * (1.f / (float)NN);
    }
    if (tid < 32 * 8) sWo[tid] = Wo[tid];
    #pragma unroll
    for (int it = 0; it < 8; it++) {
        int idx = tid + it * 256;
        int nl = idx >> 6, k = idx & 63;
        int n = n0 + nl;
        sQ[nl][k] = (n < NN) ? g_Q[(size_t)n * 64 + k] : 0.f;
    }
    #pragma unroll
    for (int it = 0; it < 4; it++) {
        int idx = tid + it * 256;
        int nl = idx >> 5, k = idx & 31;
        int n = n0 + nl;
        sH[nl][k] = (n < NN) ? g_hidden[(size_t)n * 32 + k] : 0.f;
    }
    __syncthreads();

    int nl = tid >> 3;
    int c = tid & 7;
    int n = n0 + nl;
    if (n >= NN) return;

    float acc = bo[c];
    #pragma unroll
    for (int hc = 0; hc < 32; hc++)
        acc = fmaf(sH[nl][hc], sWo[hc * 8 + c], acc);

    float tsum = 0.f;
    #pragma unroll
    for (int h = 0; h < 4; h++) {
        float num = 0.f, den = CSTV;
        #pragma unroll
        for (int i = 0; i < 16; i++) {
            float q = sQ[nl][h * 16 + i];
            num = fmaf(q, sTele[h * 128 + i * 8 + c], num);
            den = fmaf(q, sTele[512 + h * 16 + i], den);
        }
        tsum += num / den;
    }
    out[(size_t)n * 8 + c] = acc + teleport[0] * tsum;
}

// ---------------- launch ----------------
extern "C" void kernel_launch(void* const* d_in, const int* in_sizes, int n_in,
                              void* d_out, int out_size) {
    const float* nf  = (const float*)d_in[0];
    const void*  ei  = d_in[1];
    const float* Wi  = (const float*)d_in[2];
    const float* bi  = (const float*)d_in[3];
    const float* Wq  = (const float*)d_in[4];
    const float* bq  = (const float*)d_in[5];
    const float* Wk  = (const float*)d_in[6];
    const float* bk  = (const float*)d_in[7];
    const float* Wv  = (const float*)d_in[8];
    const float* bv  = (const float*)d_in[9];
    const float* Wo  = (const float*)d_in[10];
    const float* bo  = (const float*)d_in[11];
    const float* hw  = (const float*)d_in[12];
    const float* hdw = (const float*)d_in[13];
    const float* tp  = (const float*)d_in[14];
    float* out = (float*)d_out;

    // Slot 4 is what ncu captures (empirical, rounds 4-15). Diagnostic probe there:
    // an spmm2-mainloop replica at 1/4 grid. Its writes (g_x) are overwritten by
    // k_gemm1 immediately after, so output is unchanged.
    k_detect<<<1, 32>>>(ei);
    k_zero<<<(NN + 255) / 256, 256>>>();
    k_deg<<<(EE + 255) / 256, 256>>>(ei);
    k_probe<<<PROBE_N, 160>>>();
    k_gemm1<<<(NN + 63) / 64, 256>>>(nf, Wi, bi);
    k_dinv<<<(NN + 255) / 256, 256>>>();
    k_scan<<<1, 1024>>>();
    k_fill<<<(EE + 255) / 256, 256>>>(ei);

    k_gemm2<<<(NN + 63) / 64, 256>>>(Wq, bq, Wk, bk, Wv, bv);
    k_tele<<<(NN + 31) / 32, 576>>>();

    k_spmm1<<<NN, 160>>>(hw, hdw);   // hop 0: rank-1 fp32 gather + fused contraction
    k_spmm2<<<NN, 160>>>(hw, hdw);   // hop 1: bf16 dense gather + fused contraction

    k_out<<<(NN + 31) / 32, 256>>>(Wo, bo, tp, out);
}

// round 17
// speedup vs baseline: 1.1011x; 1.1011x over previous
#include <cuda_runtime.h>
#include <cuda_bf16.h>
#include <math.h>

#define NN 50000
#define EE 800000
#define FF 500
#define SW 576        // hop-2 state per node: 512 (M1) + 64 (Kf1)
#define SW4 144       // state width in float4 (fp32) / uint2 (bf16)
#define CSTV 1e-5f

// ---------------- static device scratch (no runtime allocation) ----------------
__device__ __align__(16) float g_x[(size_t)NN * 64];
__device__ __align__(16) float g_Q[(size_t)NN * 64];
__device__ __align__(16) float g_kv[(size_t)NN * 96];          // [0..63]=Kf0, [64..95]=V0 (fp32)
__device__ __align__(16) __nv_bfloat16 g_sb[(size_t)NN * SW];  // [M1 | Kf1] in bf16
__device__ __align__(16) float g_hidden[(size_t)NN * 32];
__device__ int   g_deg[NN];
__device__ float g_dinv[NN];
__device__ int   g_off[NN + 1];
__device__ int   g_cnt[NN];
__device__ __align__(16) uint2 g_epk[EE];   // per edge: (src, __float_as_uint(scale))
__device__ float g_tele[SW];     // teleport sums: 512 of M0, 64 of Kf0
__device__ int   g_is64;         // edge_index dtype flag (1 = int64, 0 = int32)

// ---------------- packed f32x2 helpers (free-pack FFMA2 path) ----------------
__device__ __forceinline__ unsigned long long pack2(float lo, float hi) {
    unsigned long long r;
    asm("mov.b64 %0, {%1, %2};" : "=l"(r) : "f"(lo), "f"(hi));
    return r;
}
__device__ __forceinline__ void ffma2(unsigned long long& d, unsigned long long a, unsigned long long b) {
    asm("fma.rn.f32x2 %0, %1, %2, %0;" : "+l"(d) : "l"(a), "l"(b));
}
__device__ __forceinline__ float2 unpack2(unsigned long long v) {
    float lo, hi;
    asm("mov.b64 {%0, %1}, %2;" : "=f"(lo), "=f"(hi) : "l"(v));
    return make_float2(lo, hi);
}
// bf16x2 word -> packed f32x2 {elem0, elem1}; exact (bf16 = truncated f32)
__device__ __forceinline__ unsigned long long bfw2f2(unsigned u) {
    unsigned lo = u << 16;
    unsigned hi = u & 0xFFFF0000u;
    unsigned long long r;
    asm("mov.b64 %0, {%1, %2};" : "=l"(r) : "r"(lo), "r"(hi));
    return r;
}

// ---------------- dtype detection (warp-parallel) ----------------
__global__ void k_detect(const void* __restrict__ ei) {
    const long long* p = (const long long*)ei;
    int t = threadIdx.x;
    int bad = 0;
    for (int i = t; i < 1024; i += 32) {
        long long v = p[i];
        if (v < 0 || v >= NN) bad = 1;
    }
    unsigned m = __ballot_sync(0xFFFFFFFFu, bad);
    if (t == 0) g_is64 = (m == 0) ? 1 : 0;
}

__device__ __forceinline__ int edge_at(const void* __restrict__ ei, int half, int e, int is64) {
    if (is64) return (int)((const long long*)ei)[(size_t)half * EE + e];
    return ((const int*)ei)[(size_t)half * EE + e];
}

// ---------------- zero counters ----------------
__global__ void k_zero() {
    int i = blockIdx.x * blockDim.x + threadIdx.x;
    if (i < NN) { g_deg[i] = 0; g_cnt[i] = 0; }
    if (i < SW) g_tele[i] = 0.f;
}

// ---------------- in-degree over col ----------------
__global__ void k_deg(const void* __restrict__ ei) {
    int e = blockIdx.x * blockDim.x + threadIdx.x;
    int is64 = g_is64;
    if (e < EE) atomicAdd(&g_deg[edge_at(ei, 1, e, is64)], 1);
}

// ---------------- deg^-1 ----------------
__global__ void k_dinv() {
    int i = blockIdx.x * blockDim.x + threadIdx.x;
    if (i < NN) {
        int d = g_deg[i];
        g_dinv[i] = d > 0 ? 1.f / (float)d : 0.f;
    }
}

// ---------------- exclusive scan of deg -> CSR offsets (single block) ----------------
__global__ void k_scan() {
    __shared__ int s[1024];
    int tid = threadIdx.x;
    const int CH = (NN + 1023) / 1024;
    int st = tid * CH;
    int en = st + CH; if (en > NN) en = NN;
    int sum = 0;
    for (int i = st; i < en; i++) sum += g_deg[i];
    s[tid] = sum;
    __syncthreads();
    for (int d = 1; d < 1024; d <<= 1) {
        int v = 0;
        if (tid >= d) v = s[tid - d];
        __syncthreads();
        if (tid >= d) s[tid] += v;
        __syncthreads();
    }
    int run = (tid > 0) ? s[tid - 1] : 0;
    for (int i = st; i < en; i++) { g_off[i] = run; run += g_deg[i]; }
    if (tid == 1023) g_off[NN] = s[1023];
}

// ---------------- fill CSR (grouped by destination) + packed per-edge meta ----------------
__global__ void k_fill(const void* __restrict__ ei) {
    int e = blockIdx.x * blockDim.x + threadIdx.x;
    int is64 = g_is64;
    if (e < EE) {
        int c = edge_at(ei, 1, e, is64);
        int r = edge_at(ei, 0, e, is64);
        int pos = g_off[c] + atomicAdd(&g_cnt[c], 1);
        g_epk[pos] = make_uint2((unsigned)r, __float_as_uint(g_dinv[r]));  // norm = deg_inv[row[e]]
    }
}

// ---------------- x = relu(node_feat @ Wi + bi)   [N,500]x[500,64] ----------------
__global__ void __launch_bounds__(256) k_gemm1(const float* __restrict__ A,
                                               const float* __restrict__ Wi,
                                               const float* __restrict__ bi) {
    __shared__ float As[64][33];
    __shared__ __align__(16) float Bs[32 * 64];
    int tid = threadIdx.x;
    int row0 = blockIdx.x * 64;
    int tc = tid & 15;
    int tr = tid >> 4;
    float acc[4][4];
    #pragma unroll
    for (int i = 0; i < 4; i++)
        #pragma unroll
        for (int j = 0; j < 4; j++) acc[i][j] = 0.f;

    for (int k0 = 0; k0 < FF; k0 += 32) {
        #pragma unroll
        for (int it = 0; it < 8; it++) {
            int idx = tid + it * 256;
            int r = idx >> 5, kk = idx & 31;
            int gr = row0 + r, gk = k0 + kk;
            As[r][kk] = (gr < NN && gk < FF) ? A[(size_t)gr * FF + gk] : 0.f;
        }
        #pragma unroll
        for (int it = 0; it < 8; it++) {
            int idx = tid + it * 256;
            int kk = idx >> 6, c = idx & 63;
            int gk = k0 + kk;
            Bs[idx] = (gk < FF) ? Wi[gk * 64 + c] : 0.f;
        }
        __syncthreads();
        #pragma unroll
        for (int kk = 0; kk < 32; kk++) {
            float a[4];
            #pragma unroll
            for (int i = 0; i < 4; i++) a[i] = As[tr * 4 + i][kk];
            float4 bv = *(const float4*)&Bs[kk * 64 + tc * 4];
            float b[4] = {bv.x, bv.y, bv.z, bv.w};
            #pragma unroll
            for (int i = 0; i < 4; i++)
                #pragma unroll
                for (int j = 0; j < 4; j++)
                    acc[i][j] = fmaf(a[i], b[j], acc[i][j]);
        }
        __syncthreads();
    }
    #pragma unroll
    for (int i = 0; i < 4; i++) {
        int r = row0 + tr * 4 + i;
        if (r < NN) {
            #pragma unroll
            for (int j = 0; j < 4; j++) {
                int c = tc * 4 + j;
                float v = acc[i][j] + bi[c];
                g_x[(size_t)r * 64 + c] = v > 0.f ? v : 0.f;
            }
        }
    }
}

// ---------------- fused QKV projections  [N,64]x[64,160] ----------------
// cols 0..63 -> Q (1+elu), 64..127 -> Kf0 (1+elu, kv[0..63]), 128..159 -> V0 (kv[64..95])
__global__ void __launch_bounds__(256) k_gemm2(const float* __restrict__ Wq, const float* __restrict__ bq,
                                               const float* __restrict__ Wk, const float* __restrict__ bk,
                                               const float* __restrict__ Wv, const float* __restrict__ bv) {
    __shared__ float Xs[64][33];
    __shared__ float Ws[32][160];
    int tid = threadIdx.x;
    int row0 = blockIdx.x * 64;
    int tc = tid & 15;
    int tr = tid >> 4;
    float acc[4][10];
    #pragma unroll
    for (int i = 0; i < 4; i++)
        #pragma unroll
        for (int j = 0; j < 10; j++) acc[i][j] = 0.f;

    for (int kt = 0; kt < 2; kt++) {
        #pragma unroll
        for (int it = 0; it < 8; it++) {
            int idx = tid + it * 256;
            int r = idx >> 5, kk = idx & 31;
            int gr = row0 + r;
            Xs[r][kk] = (gr < NN) ? g_x[(size_t)gr * 64 + kt * 32 + kk] : 0.f;
        }
        #pragma unroll
        for (int it = 0; it < 20; it++) {
            int idx = tid + it * 256;
            int kk = idx / 160, c = idx % 160;
            int gk = kt * 32 + kk;
            float w;
            if (c < 64)       w = Wq[gk * 64 + c];
            else if (c < 128) w = Wk[gk * 64 + (c - 64)];
            else              w = Wv[gk * 32 + (c - 128)];
            Ws[kk][c] = w;
        }
        __syncthreads();
        #pragma unroll
        for (int kk = 0; kk < 32; kk++) {
            float a[4];
            #pragma unroll
            for (int i = 0; i < 4; i++) a[i] = Xs[tr * 4 + i][kk];
            float b[10];
            #pragma unroll
            for (int j = 0; j < 10; j++) b[j] = Ws[kk][tc * 10 + j];
            #pragma unroll
            for (int i = 0; i < 4; i++)
                #pragma unroll
                for (int j = 0; j < 10; j++)
                    acc[i][j] = fmaf(a[i], b[j], acc[i][j]);
        }
        __syncthreads();
    }

    #pragma unroll
    for (int i = 0; i < 4; i++) {
        int r = row0 + tr * 4 + i;
        if (r >= NN) continue;
        #pragma unroll
        for (int j = 0; j < 10; j++) {
            int c = tc * 10 + j;
            float v = acc[i][j];
            if (c < 64) {
                v += bq[c];
                v = v > 0.f ? 1.f + v : expf(v);   // 1 + elu
                g_Q[(size_t)r * 64 + c] = v;
            } else if (c < 128) {
                int cc = c - 64;
                v += bk[cc];
                v = v > 0.f ? 1.f + v : expf(v);
                g_kv[(size_t)r * 96 + cc] = v;
            } else {
                int cc = c - 128;
                v += bv[cc];
                g_kv[(size_t)r * 96 + 64 + cc] = v;
            }
        }
    }
}

// ---------------- teleport sums over M0 = Kf0 (x) V0 and Kf0 ----------------
__global__ void __launch_bounds__(576) k_tele() {
    __shared__ float skv[96];
    int t = threadIdx.x;
    int n0 = blockIdx.x * 32;
    float tele = 0.f;
    for (int nn = 0; nn < 32; nn++) {
        int n = n0 + nn;
        if (n >= NN) break;
        __syncthreads();
        if (t < 96) skv[t] = g_kv[(size_t)n * 96 + t];
        __syncthreads();
        if (t < 512) tele += skv[t >> 3] * skv[64 + (((t >> 7) << 3) | (t & 7))];
        else         tele += skv[t - 512];
    }
    atomicAdd(&g_tele[t], tele);
}

// ---------------- hop 1: rank-1 on-the-fly gather (fp32 kv, FFMA2 accumulate) ----------------
// 160 threads, one block per destination. Thread t<144 owns state float4 t of [M1|Kf1].
__global__ void __launch_bounds__(160) k_spmm1(const float* __restrict__ hopwise,
                                               const float* __restrict__ headwise) {
    __shared__ float sQ[64];
    __shared__ float sHh[32];
    __shared__ float sCc[4];
    __shared__ float sG[4];
    int n = blockIdx.x;
    int t = threadIdx.x;

    if (t < 4) {   // gamma0[h] = hopwise[1] * softmax_h(headwise[:,0])[h]
        float w0 = headwise[0], w1 = headwise[2], w2 = headwise[4], w3 = headwise[6];
        float mx = fmaxf(fmaxf(w0, w1), fmaxf(w2, w3));
        float e0 = expf(w0 - mx), e1 = expf(w1 - mx), e2 = expf(w2 - mx), e3 = expf(w3 - mx);
        float inv = 1.f / (e0 + e1 + e2 + e3);
        float me = (t == 0) ? e0 : (t == 1) ? e1 : (t == 2) ? e2 : e3;
        sG[t] = hopwise[1] * me * inv;
    }
    if (t >= 32 && t < 96) sQ[t - 32] = g_Q[(size_t)n * 64 + (t - 32)];

    int beg = g_off[n], end = g_off[n + 1];
    unsigned long long accA = pack2(0.f, 0.f);
    unsigned long long accB = accA;

    if (t < 128) {
        int kidx  = t >> 1;                         // Kf0 scalar index h*16+i
        int v4idx = 16 + ((t >> 5) << 1) + (t & 1); // V0 float4 index within 24-float4 row
        int e = beg;
        for (; e + 1 < end; e += 2) {
            uint2 m0 = __ldg(&g_epk[e]);
            uint2 m1 = __ldg(&g_epk[e + 1]);
            const float4* r0 = (const float4*)(g_kv + (size_t)m0.x * 96);
            const float4* r1 = (const float4*)(g_kv + (size_t)m1.x * 96);
            float k0 = __ldg((const float*)r0 + kidx);
            float k1 = __ldg((const float*)r1 + kidx);
            float4 v0 = __ldg(r0 + v4idx);
            float4 v1 = __ldg(r1 + v4idx);
            float sk0 = __uint_as_float(m0.y) * k0;
            float sk1 = __uint_as_float(m1.y) * k1;
            unsigned long long p0 = pack2(sk0, sk0);
            unsigned long long p1 = pack2(sk1, sk1);
            ffma2(accA, p0, pack2(v0.x, v0.y));
            ffma2(accB, p0, pack2(v0.z, v0.w));
            ffma2(accA, p1, pack2(v1.x, v1.y));
            ffma2(accB, p1, pack2(v1.z, v1.w));
        }
        if (e < end) {
            uint2 m = __ldg(&g_epk[e]);
            const float4* r = (const float4*)(g_kv + (size_t)m.x * 96);
            float sk = __uint_as_float(m.y) * __ldg((const float*)r + kidx);
            float4 v = __ldg(r + v4idx);
            unsigned long long p = pack2(sk, sk);
            ffma2(accA, p, pack2(v.x, v.y));
            ffma2(accB, p, pack2(v.z, v.w));
        }
    } else if (t < 144) {
        int k4 = t - 128;                           // Kf0 float4 index
        int e = beg;
        for (; e + 1 < end; e += 2) {
            uint2 m0 = __ldg(&g_epk[e]);
            uint2 m1 = __ldg(&g_epk[e + 1]);
            float4 v0 = __ldg((const float4*)(g_kv + (size_t)m0.x * 96) + k4);
            float4 v1 = __ldg((const float4*)(g_kv + (size_t)m1.x * 96) + k4);
            float c0 = __uint_as_float(m0.y);
            float c1 = __uint_as_float(m1.y);
            unsigned long long p0 = pack2(c0, c0);
            unsigned long long p1 = pack2(c1, c1);
            ffma2(accA, p0, pack2(v0.x, v0.y));
            ffma2(accB, p0, pack2(v0.z, v0.w));
            ffma2(accA, p1, pack2(v1.x, v1.y));
            ffma2(accB, p1, pack2(v1.z, v1.w));
        }
        if (e < end) {
            uint2 m = __ldg(&g_epk[e]);
            float4 v = __ldg((const float4*)(g_kv + (size_t)m.x * 96) + k4);
            float c = __uint_as_float(m.y);
            unsigned long long p = pack2(c, c);
            ffma2(accA, p, pack2(v.x, v.y));
            ffma2(accB, p, pack2(v.z, v.w));
        }
    }

    float2 pa = unpack2(accA);
    float2 pb = unpack2(accB);
    float4 acc = make_float4(pa.x, pa.y, pb.x, pb.y);

    // publish [M1|Kf1] state for hop 2 in bf16 (one 8B store per thread)
    if (t < SW4) {
        __nv_bfloat162 p0 = __floats2bfloat162_rn(acc.x, acc.y);
        __nv_bfloat162 p1 = __floats2bfloat162_rn(acc.z, acc.w);
        uint2 u;
        u.x = *reinterpret_cast<unsigned*>(&p0);
        u.y = *reinterpret_cast<unsigned*>(&p1);
        ((uint2*)(g_sb + (size_t)n * SW))[t] = u;
    }
    __syncthreads();

    // contraction (fp32 accumulators)
    if (t < 128) {
        int h = t >> 5;
        int kidx = t >> 1;
        int j0 = (t & 1) * 4;
        float q = sQ[kidx];
        float r0 = q * acc.x, r1 = q * acc.y, r2 = q * acc.z, r3 = q * acc.w;
        #pragma unroll
        for (int off = 2; off <= 16; off <<= 1) {
            r0 += __shfl_xor_sync(0xFFFFFFFFu, r0, off);
            r1 += __shfl_xor_sync(0xFFFFFFFFu, r1, off);
            r2 += __shfl_xor_sync(0xFFFFFFFFu, r2, off);
            r3 += __shfl_xor_sync(0xFFFFFFFFu, r3, off);
        }
        int lane = t & 31;
        if (lane < 2) {
            sHh[h * 8 + j0 + 0] = r0;
            sHh[h * 8 + j0 + 1] = r1;
            sHh[h * 8 + j0 + 2] = r2;
            sHh[h * 8 + j0 + 3] = r3;
        }
    } else if (t < 144) {
        int f = (t - 128) * 4;
        float c = sQ[f] * acc.x + sQ[f + 1] * acc.y + sQ[f + 2] * acc.z + sQ[f + 3] * acc.w;
        #pragma unroll
        for (int off = 1; off <= 2; off <<= 1)
            c += __shfl_xor_sync(0x0000FFFFu, c, off);
        int lane = t & 31;
        if ((lane & 3) == 0) sCc[lane >> 2] = c;
    }
    __syncthreads();

    if (t < 32) {
        int h = t >> 3;
        float v0 = g_kv[(size_t)n * 96 + 64 + t];
        g_hidden[(size_t)n * 32 + t] = hopwise[0] * v0 + sG[h] * sHh[t] / (sCc[h] + CSTV);
    }
}

// ---------------- hop 2: bf16 gather, shift/mask convert + FFMA2 accumulate ----------------
__global__ void __launch_bounds__(160) k_spmm2(const float* __restrict__ hopwise,
                                               const float* __restrict__ headwise) {
    __shared__ float sQ[64];
    __shared__ float sHh[32];
    __shared__ float sCc[4];
    __shared__ float sG[4];
    int n = blockIdx.x;
    int t = threadIdx.x;

    if (t < 4) {   // gamma1[h] = hopwise[2] * softmax_h(headwise[:,1])[h]
        float w0 = headwise[1], w1 = headwise[3], w2 = headwise[5], w3 = headwise[7];
        float mx = fmaxf(fmaxf(w0, w1), fmaxf(w2, w3));
        float e0 = expf(w0 - mx), e1 = expf(w1 - mx), e2 = expf(w2 - mx), e3 = expf(w3 - mx);
        float inv = 1.f / (e0 + e1 + e2 + e3);
        float me = (t == 0) ? e0 : (t == 1) ? e1 : (t == 2) ? e2 : e3;
        sG[t] = hopwise[2] * me * inv;
    }
    if (t >= 32 && t < 96) sQ[t - 32] = g_Q[(size_t)n * 64 + (t - 32)];

    int beg = g_off[n], end = g_off[n + 1];
    unsigned long long accA = pack2(0.f, 0.f);
    unsigned long long accB = accA;
    if (t < SW4) {
        int e = beg;
        for (; e + 1 < end; e += 2) {
            uint2 m0 = __ldg(&g_epk[e]);
            uint2 m1 = __ldg(&g_epk[e + 1]);
            uint2 u0 = __ldg((const uint2*)(g_sb + (size_t)m0.x * SW) + t);
            uint2 u1 = __ldg((const uint2*)(g_sb + (size_t)m1.x * SW) + t);
            float c0 = __uint_as_float(m0.y);
            float c1 = __uint_as_float(m1.y);
            unsigned long long p0 = pack2(c0, c0);
            unsigned long long p1 = pack2(c1, c1);
            ffma2(accA, p0, bfw2f2(u0.x));
            ffma2(accB, p0, bfw2f2(u0.y));
            ffma2(accA, p1, bfw2f2(u1.x));
            ffma2(accB, p1, bfw2f2(u1.y));
        }
        if (e < end) {
            uint2 m = __ldg(&g_epk[e]);
            uint2 u = __ldg((const uint2*)(g_sb + (size_t)m.x * SW) + t);
            float c = __uint_as_float(m.y);
            unsigned long long p = pack2(c, c);
            ffma2(accA, p, bfw2f2(u.x));
            ffma2(accB, p, bfw2f2(u.y));
        }
    }
    float2 pa = unpack2(accA);
    float2 pb = unpack2(accB);
    float4 acc = make_float4(pa.x, pa.y, pb.x, pb.y);
    __syncthreads();

    if (t < 128) {
        int h = t >> 5;
        int kidx = t >> 1;
        int j0 = (t & 1) * 4;
        float q = sQ[kidx];
        float r0 = q * acc.x, r1 = q * acc.y, r2 = q * acc.z, r3 = q * acc.w;
        #pragma unroll
        for (int off = 2; off <= 16; off <<= 1) {
            r0 += __shfl_xor_sync(0xFFFFFFFFu, r0, off);
            r1 += __shfl_xor_sync(0xFFFFFFFFu, r1, off);
            r2 += __shfl_xor_sync(0xFFFFFFFFu, r2, off);
            r3 += __shfl_xor_sync(0xFFFFFFFFu, r3, off);
        }
        int lane = t & 31;
        if (lane < 2) {
            sHh[h * 8 + j0 + 0] = r0;
            sHh[h * 8 + j0 + 1] = r1;
            sHh[h * 8 + j0 + 2] = r2;
            sHh[h * 8 + j0 + 3] = r3;
        }
    } else if (t < 144) {
        int f = (t - 128) * 4;
        float c = sQ[f] * acc.x + sQ[f + 1] * acc.y + sQ[f + 2] * acc.z + sQ[f + 3] * acc.w;
        #pragma unroll
        for (int off = 1; off <= 2; off <<= 1)
            c += __shfl_xor_sync(0x0000FFFFu, c, off);
        int lane = t & 31;
        if ((lane & 3) == 0) sCc[lane >> 2] = c;
    }
    __syncthreads();

    if (t < 32) {
        int h = t >> 3;
        g_hidden[(size_t)n * 32 + t] += sG[h] * sHh[t] / (sCc[h] + CSTV);
    }
}

// ---------------- output projection + teleport term ----------------
__global__ void __launch_bounds__(256) k_out(const float* __restrict__ Wo,
                                             const float* __restrict__ bo,
                                             const float* __restrict__ teleport,
                                             float* __restrict__ out) {
    __shared__ float sTele[SW];
    __shared__ float sWo[32 * 8];
    __shared__ float sQ[32][64];
    __shared__ float sH[32][32];
    int tid = threadIdx.x;
    int n0 = blockIdx.x * 32;

    #pragma unroll
    for (int it = 0; it < 3; it++) {
        int idx = tid + it * 256;
        if (idx < SW) sTele[idx] = g_tele[idx] * (1.f / (float)NN);
    }
    if (tid < 32 * 8) sWo[tid] = Wo[tid];
    #pragma unroll
    for (int it = 0; it < 8; it++) {
        int idx = tid + it * 256;
        int nl = idx >> 6, k = idx & 63;
        int n = n0 + nl;
        sQ[nl][k] = (n < NN) ? g_Q[(size_t)n * 64 + k] : 0.f;
    }
    #pragma unroll
    for (int it = 0; it < 4; it++) {
        int idx = tid + it * 256;
        int nl = idx >> 5, k = idx & 31;
        int n = n0 + nl;
        sH[nl][k] = (n < NN) ? g_hidden[(size_t)n * 32 + k] : 0.f;
    }
    __syncthreads();

    int nl = tid >> 3;
    int c = tid & 7;
    int n = n0 + nl;
    if (n >= NN) return;

    float acc = bo[c];
    #pragma unroll
    for (int hc = 0; hc < 32; hc++)
        acc = fmaf(sH[nl][hc], sWo[hc * 8 + c], acc);

    float tsum = 0.f;
    #pragma unroll
    for (int h = 0; h < 4; h++) {
        float num = 0.f, den = CSTV;
        #pragma unroll
        for (int i = 0; i < 16; i++) {
            float q = sQ[nl][h * 16 + i];
            num = fmaf(q, sTele[h * 128 + i * 8 + c], num);
            den = fmaf(q, sTele[512 + h * 16 + i], den);
        }
        tsum += num / den;
    }
    out[(size_t)n * 8 + c] = acc + teleport[0] * tsum;
}

// ---------------- launch ----------------
extern "C" void kernel_launch(void* const* d_in, const int* in_sizes, int n_in,
                              void* d_out, int out_size) {
    const float* nf  = (const float*)d_in[0];
    const void*  ei  = d_in[1];
    const float* Wi  = (const float*)d_in[2];
    const float* bi  = (const float*)d_in[3];
    const float* Wq  = (const float*)d_in[4];
    const float* bq  = (const float*)d_in[5];
    const float* Wk  = (const float*)d_in[6];
    const float* bk  = (const float*)d_in[7];
    const float* Wv  = (const float*)d_in[8];
    const float* bv  = (const float*)d_in[9];
    const float* Wo  = (const float*)d_in[10];
    const float* bo  = (const float*)d_in[11];
    const float* hw  = (const float*)d_in[12];
    const float* hdw = (const float*)d_in[13];
    const float* tp  = (const float*)d_in[14];
    float* out = (float*)d_out;

    k_detect<<<1, 32>>>(ei);
    k_zero<<<(NN + 255) / 256, 256>>>();
    k_deg<<<(EE + 255) / 256, 256>>>(ei);
    k_gemm1<<<(NN + 63) / 64, 256>>>(nf, Wi, bi);
    k_dinv<<<(NN + 255) / 256, 256>>>();
    k_scan<<<1, 1024>>>();
    k_fill<<<(EE + 255) / 256, 256>>>(ei);

    k_gemm2<<<(NN + 63) / 64, 256>>>(Wq, bq, Wk, bk, Wv, bv);
    k_tele<<<(NN + 31) / 32, 576>>>();

    k_spmm1<<<NN, 160>>>(hw, hdw);   // hop 0: rank-1 fp32 gather, FFMA2 accumulate
    k_spmm2<<<NN, 160>>>(hw, hdw);   // hop 1: bf16 gather, shift/mask + FFMA2 accumulate

    k_out<<<(NN + 31) / 32, 256>>>(Wo, bo, tp, out);
}